// round 1
// baseline (speedup 1.0000x reference)
#include <cuda_runtime.h>

#define N_NODES   50000
#define N_EDGES   800000
#define IN_DIM    1280
#define HID       512
#define EMB       64
#define LN_EPS    1e-5f
#define NEG_SLOPE 0.2f

// ---------------- scratch (static device globals; no allocation) ----------------
__device__ float g_feat[N_NODES * EMB];   // 12.8 MB
__device__ float g_el[N_NODES];
__device__ float g_er[N_NODES];
__device__ float g_m[N_NODES];
__device__ float g_s[N_NODES];
__device__ float g_e[N_EDGES];            // 3.2 MB

constexpr int BM = 32;          // nodes per block
constexpr int BK = 32;          // K tile
constexpr int XS = HID + 4;     // padded stride for LN'd row in smem (bank-spread)

// =================================================================================
// Kernel 1: x = LN(ReLU(features@W1 + b1)); feat = x@Wg; el = feat@attn_l; er = feat@attn_r
// One block = 32 nodes. Phase 1: tiled fp32 GEMM (full 512-wide row per block so
// LayerNorm fuses in-register). Phase 2: GEMM2 from smem with Wg streamed via L1.
// =================================================================================
__global__ __launch_bounds__(256) void node_kernel(
    const float* __restrict__ A,   const float* __restrict__ W1,
    const float* __restrict__ b1,  const float* __restrict__ ln_g,
    const float* __restrict__ ln_b,const float* __restrict__ Wg,
    const float* __restrict__ attn_l, const float* __restrict__ attn_r)
{
    extern __shared__ float Bs[];           // phase1: [BK][HID] flat (16384 f); phase2: XN [BM][XS] (16512 f)
    __shared__ float As[BM][BK + 4];

    const int tid   = threadIdx.x;
    const int warp  = tid >> 5;
    const int lane  = tid & 31;
    const int node0 = blockIdx.x * BM;

    float acc[4][16];
#pragma unroll
    for (int r = 0; r < 4; r++)
#pragma unroll
        for (int j = 0; j < 16; j++) acc[r][j] = 0.f;

    // A-tile load mapping: thread -> (row, 4 consecutive k)
    const int  lr     = tid >> 3;         // 0..31
    const int  lk     = (tid & 7) * 4;    // 0,4,...,28
    const int  arow   = node0 + lr;
    const bool avalid = arow < N_NODES;
    const float* Aptr = A + (size_t)arow * IN_DIM;

    for (int k0 = 0; k0 < IN_DIM; k0 += BK) {
        float4 av = make_float4(0.f, 0.f, 0.f, 0.f);
        if (avalid) av = *(const float4*)(Aptr + k0 + lk);
        As[lr][lk + 0] = av.x; As[lr][lk + 1] = av.y;
        As[lr][lk + 2] = av.z; As[lr][lk + 3] = av.w;

        // W1 tile: 32 x 512 floats, 16 float4 per thread, fully coalesced
#pragma unroll
        for (int p = 0; p < 16; p++) {
            int idx = p * 1024 + tid * 4;
            int kr = idx >> 9, c = idx & 511;
            *(float4*)&Bs[kr * HID + c] =
                *(const float4*)(W1 + (size_t)(k0 + kr) * HID + c);
        }
        __syncthreads();

#pragma unroll 8
        for (int kk = 0; kk < BK; kk++) {
            const float a0 = As[warp * 4 + 0][kk];
            const float a1 = As[warp * 4 + 1][kk];
            const float a2 = As[warp * 4 + 2][kk];
            const float a3 = As[warp * 4 + 3][kk];
#pragma unroll
            for (int j = 0; j < 16; j++) {
                const float bv = Bs[kk * HID + lane + 32 * j];
                acc[0][j] = fmaf(a0, bv, acc[0][j]);
                acc[1][j] = fmaf(a1, bv, acc[1][j]);
                acc[2][j] = fmaf(a2, bv, acc[2][j]);
                acc[3][j] = fmaf(a3, bv, acc[3][j]);
            }
        }
        __syncthreads();
    }

    // ---- bias + ReLU + LayerNorm; write normalized rows into smem (reuse Bs) ----
    float gg[16], bb[16], bias[16];
#pragma unroll
    for (int j = 0; j < 16; j++) {
        const int c = lane + 32 * j;
        gg[j] = ln_g[c]; bb[j] = ln_b[c]; bias[j] = b1[c];
    }
#pragma unroll
    for (int r = 0; r < 4; r++) {
        float sum = 0.f, sq = 0.f;
#pragma unroll
        for (int j = 0; j < 16; j++) {
            float v = acc[r][j] + bias[j];
            v = v > 0.f ? v : 0.f;
            acc[r][j] = v;
            sum += v;
            sq = fmaf(v, v, sq);
        }
#pragma unroll
        for (int o = 16; o >= 1; o >>= 1) {
            sum += __shfl_xor_sync(0xffffffffu, sum, o);
            sq  += __shfl_xor_sync(0xffffffffu, sq,  o);
        }
        const float mu   = sum * (1.f / HID);
        const float var  = sq * (1.f / HID) - mu * mu;
        const float rstd = rsqrtf(var + LN_EPS);
        const int   row  = warp * 4 + r;
#pragma unroll
        for (int j = 0; j < 16; j++) {
            const float xn = (acc[r][j] - mu) * rstd * gg[j] + bb[j];
            Bs[row * XS + lane + 32 * j] = xn;
        }
    }
    __syncthreads();

    // ---- Phase 2: feat = xn @ Wg  (thread -> 1 row x 8 cols), then el/er ----
    const int prow = tid >> 3;            // 0..31
    const int c0   = (tid & 7) * 8;       // 0..56
    float f[8];
#pragma unroll
    for (int i = 0; i < 8; i++) f[i] = 0.f;

#pragma unroll 4
    for (int k = 0; k < HID; k++) {
        const float  xv = Bs[prow * XS + k];
        const float4 w0 = *(const float4*)(Wg + (size_t)k * EMB + c0);
        const float4 w1 = *(const float4*)(Wg + (size_t)k * EMB + c0 + 4);
        f[0] = fmaf(xv, w0.x, f[0]); f[1] = fmaf(xv, w0.y, f[1]);
        f[2] = fmaf(xv, w0.z, f[2]); f[3] = fmaf(xv, w0.w, f[3]);
        f[4] = fmaf(xv, w1.x, f[4]); f[5] = fmaf(xv, w1.y, f[5]);
        f[6] = fmaf(xv, w1.z, f[6]); f[7] = fmaf(xv, w1.w, f[7]);
    }

    float elp = 0.f, erp = 0.f;
#pragma unroll
    for (int i = 0; i < 8; i++) {
        elp = fmaf(f[i], attn_l[c0 + i], elp);
        erp = fmaf(f[i], attn_r[c0 + i], erp);
    }
#pragma unroll
    for (int o = 4; o >= 1; o >>= 1) {
        elp += __shfl_down_sync(0xffffffffu, elp, o);
        erp += __shfl_down_sync(0xffffffffu, erp, o);
    }

    const int gnode = node0 + prow;
    if (gnode < N_NODES) {
        *(float4*)(g_feat + (size_t)gnode * EMB + c0)     = make_float4(f[0], f[1], f[2], f[3]);
        *(float4*)(g_feat + (size_t)gnode * EMB + c0 + 4) = make_float4(f[4], f[5], f[6], f[7]);
        if ((tid & 7) == 0) { g_el[gnode] = elp; g_er[gnode] = erp; }
    }
}

// ============================== Kernel 2: init ===================================
__global__ void init_kernel(float* __restrict__ out, const float* __restrict__ bias_g)
{
    const int i = blockIdx.x * blockDim.x + threadIdx.x;
    if (i < N_NODES * EMB) out[i] = bias_g[i & (EMB - 1)];
    if (i < N_NODES) { g_m[i] = __int_as_float(0xff800000); g_s[i] = 0.f; }
}

// =============== Kernel 3: edge score + segment max (float atomicMax) ===========
__global__ void edge_max_kernel(const int* __restrict__ src, const int* __restrict__ dst)
{
    const int i = blockIdx.x * blockDim.x + threadIdx.x;
    if (i >= N_EDGES) return;
    float v = g_el[src[i]] + g_er[dst[i]];
    v = v > 0.f ? v : NEG_SLOPE * v;
    g_e[i] = v;
    float* addr = &g_m[dst[i]];
    // monotone int/uint encoding: works mixed-sign with -inf init
    if (v >= 0.f) atomicMax((int*)addr, __float_as_int(v));
    else          atomicMin((unsigned int*)addr, __float_as_uint(v));
}

// =============== Kernel 4: exp + segment sum =====================================
__global__ void edge_exp_kernel(const int* __restrict__ dst)
{
    const int i = blockIdx.x * blockDim.x + threadIdx.x;
    if (i >= N_EDGES) return;
    const int d = dst[i];
    const float ex = __expf(g_e[i] - g_m[d]);
    g_e[i] = ex;
    atomicAdd(&g_s[d], ex);
}

// =============== Kernel 5: weighted scatter-aggregate (warp per edge) ============
__global__ void agg_kernel(const int* __restrict__ src, const int* __restrict__ dst,
                           float* __restrict__ out)
{
    const int w    = (blockIdx.x * blockDim.x + threadIdx.x) >> 5;
    const int lane = threadIdx.x & 31;
    if (w >= N_EDGES) return;
    const int sN = src[w], dN = dst[w];
    const float a  = g_e[w] / g_s[dN];
    const float v0 = g_feat[(size_t)sN * EMB + lane]      * a;
    const float v1 = g_feat[(size_t)sN * EMB + 32 + lane] * a;
    atomicAdd(out + (size_t)dN * EMB + lane,      v0);
    atomicAdd(out + (size_t)dN * EMB + 32 + lane, v1);
}

// =================================================================================
extern "C" void kernel_launch(void* const* d_in, const int* in_sizes, int n_in,
                              void* d_out, int out_size)
{
    const float* features = (const float*)d_in[0];
    const int*   src      = (const int*)  d_in[1];
    const int*   dst      = (const int*)  d_in[2];
    const float* W1       = (const float*)d_in[3];
    const float* b1       = (const float*)d_in[4];
    const float* ln_g     = (const float*)d_in[5];
    const float* ln_b     = (const float*)d_in[6];
    const float* Wg       = (const float*)d_in[7];
    const float* attn_l   = (const float*)d_in[8];
    const float* attn_r   = (const float*)d_in[9];
    const float* bias_g   = (const float*)d_in[10];
    float* out = (float*)d_out;

    const size_t smem = (size_t)BM * XS * sizeof(float);   // 66048 B (> 48KB: opt in)
    cudaFuncSetAttribute(node_kernel, cudaFuncAttributeMaxDynamicSharedMemorySize, (int)smem);

    node_kernel<<<(N_NODES + BM - 1) / BM, 256, smem>>>(
        features, W1, b1, ln_g, ln_b, Wg, attn_l, attn_r);

    init_kernel<<<(N_NODES * EMB + 255) / 256, 256>>>(out, bias_g);

    edge_max_kernel<<<(N_EDGES + 255) / 256, 256>>>(src, dst);
    edge_exp_kernel<<<(N_EDGES + 255) / 256, 256>>>(dst);

    // one warp per edge
    const long long agg_threads = (long long)N_EDGES * 32;
    agg_kernel<<<(int)((agg_threads + 255) / 256), 256>>>(src, dst, out);
}